// round 17
// baseline (speedup 1.0000x reference)
#include <cuda_runtime.h>
#include <cstdint>

// Haar inverse DWT2 (db1), fp32.  Inputs A,H,V,D: [8,32,256,256]; out: [8,32,512,512].
// x[2i,2j]=(A+H+V+D)/2; x[2i,2j+1]=(A+H-V-D)/2; x[2i+1,2j]=(A-H+V-D)/2; x[2i+1,2j+1]=(A-H-V+D)/2
//
// R17 probe: close the request-width bracket on the narrow side.
// Width axis measured: 128-bit (-6%), 64-bit (champion), 32-bit (this probe).
// One thread per ELEMENT: 4x LDG.32 + 2x STG.64, ~14 regs, 16.8M threads,
// block=512 (proven peak). Warp stores stay fully coalesced (256B contiguous).

__global__ void __launch_bounds__(512) idwt2_haar_kernel(
    const float* __restrict__ A,
    const float* __restrict__ H,
    const float* __restrict__ V,
    const float* __restrict__ D,
    float2* __restrict__ out)
{
    // total threads = 8*32*256*256 = 16,777,216
    const unsigned t = blockIdx.x * 512u + threadIdx.x;

    const float a = __ldg(&A[t]);
    const float h = __ldg(&H[t]);
    const float v = __ldg(&V[t]);
    const float d = __ldg(&D[t]);

    const float lp = a + h, lm = a - h;
    const float mp = v + d, mm = v - d;

    float2 even, odd;
    even.x = (lp + mp) * 0.5f;   // x[2i, 2j]
    even.y = (lp - mp) * 0.5f;   // x[2i, 2j+1]
    odd.x  = (lm + mm) * 0.5f;   // x[2i+1, 2j]
    odd.y  = (lm - mm) * 0.5f;   // x[2i+1, 2j+1]

    // t = b*65536 + i*256 + j ; even-row out f2 index = b*131072 + i*512 + j
    //                         = ((t>>8)<<9) + (t&255)
    const unsigned o = ((t >> 8) << 9) + (t & 255u);
    out[o]        = even;
    out[o + 256u] = odd;   // odd row: +512 floats = +256 float2s
}

extern "C" void kernel_launch(void* const* d_in, const int* in_sizes, int n_in,
                              void* d_out, int out_size)
{
    const float* A = (const float*)d_in[0];
    const float* H = (const float*)d_in[1];
    const float* V = (const float*)d_in[2];
    const float* D = (const float*)d_in[3];
    float2* out = (float2*)d_out;

    const unsigned n_threads = (unsigned)in_sizes[0];   // 16,777,216
    const unsigned blocks = (n_threads + 511u) / 512u;  // 32768

    idwt2_haar_kernel<<<blocks, 512>>>(A, H, V, D, out);
}